// round 1
// baseline (speedup 1.0000x reference)
#include <cuda_runtime.h>

// ---------------- problem constants ----------------
static const int BSZ   = 64;     // batch
static const int SEQ   = 256;    // sequence length
static const int DIM   = 512;    // embed dim
static const int HID   = 512;    // hidden
static const int DHID  = 1024;   // DIM + HID
static const int NGATE = 2048;   // 4*HID (per direction)
static const int MROWS = SEQ * BSZ;   // 16384
static const int NTOT  = 2 * NGATE;   // 4096 (both directions)
static const int CLS   = 5;

// ---------------- device scratch (no allocations allowed) ----------------
__device__ float g_xs  [MROWS * DIM];                 // [s*BSZ+b][d]        33.5 MB
__device__ float g_gx  [2L * SEQ * BSZ * NGATE];      // [dir][s][b][gatecol] 268 MB
__device__ float g_hbuf[2 * 2 * BSZ * HID];           // [dir][parity][b][h]
__device__ float g_hist[2L * SEQ * BSZ * HID];        // [dir][s][b][h]       67 MB
__device__ float g_pooled[BSZ * HID];

// ---------------- kernel 0: zero h state ----------------
__global__ void k_zero() {
    int i = blockIdx.x * blockDim.x + threadIdx.x;
    if (i < 4 * BSZ * HID) g_hbuf[i] = 0.0f;
}

// ---------------- kernel 1: embedding gather ----------------
// xs[s][b][:] = embed[x[b][s]][:]
__global__ void k_gather(const int* __restrict__ x, const float* __restrict__ embed) {
    int sb = blockIdx.x;            // sb = s*BSZ + b
    int b = sb & (BSZ - 1);
    int s = sb >> 6;
    int tok = x[b * SEQ + s];
    const float4* src = (const float4*)(embed + (size_t)tok * DIM);
    float4* dst = (float4*)(g_xs + (size_t)sb * DIM);
    dst[threadIdx.x] = src[threadIdx.x];   // 128 threads * 4 floats = 512
}

// ---------------- kernel 2: x-projection GEMM ----------------
// C[m][n] = sum_k xs[m][k] * W(n)[k] + bias(n),  m in [0,16384), n in [0,4096)
// n: dir = n>>11, gatecol ng = n&2047 (= g*512 + h); W row stride DHID, x-part at k offset 0.
__global__ void __launch_bounds__(256, 2)
k_gemm(const float* __restrict__ fwdW, const float* __restrict__ bwdW,
       const float* __restrict__ fwdb, const float* __restrict__ bwdb) {
    const int BM = 128, BN = 128, BK = 16, TM = 8, TN = 8;
    __shared__ __align__(16) float As[BK][BM];
    __shared__ __align__(16) float Bs[BK][BN];

    int tid = threadIdx.x;
    int tx = tid & 15, ty = tid >> 4;
    int m0 = blockIdx.y * BM;
    int n0 = blockIdx.x * BN;

    int a_r = tid >> 2;             // 0..63
    int a_c = (tid & 3) * 4;        // 0,4,8,12

    float acc[TM][TN];
#pragma unroll
    for (int i = 0; i < TM; i++)
#pragma unroll
        for (int j = 0; j < TN; j++) acc[i][j] = 0.0f;

    for (int k0 = 0; k0 < DIM; k0 += BK) {
        // load A tile (transposed into As[k][m])
#pragma unroll
        for (int rr = 0; rr < 2; rr++) {
            int r = a_r + rr * 64;
            float4 v = *(const float4*)(g_xs + (size_t)(m0 + r) * DIM + k0 + a_c);
            As[a_c + 0][r] = v.x; As[a_c + 1][r] = v.y;
            As[a_c + 2][r] = v.z; As[a_c + 3][r] = v.w;
        }
        // load B tile (W rows, stride DHID)
#pragma unroll
        for (int rr = 0; rr < 2; rr++) {
            int rl = a_r + rr * 64;
            int n = n0 + rl;
            int dir = n >> 11;
            int ng = n & 2047;
            const float* Wrow = (dir ? bwdW : fwdW) + (size_t)ng * DHID;
            float4 v = *(const float4*)(Wrow + k0 + a_c);
            Bs[a_c + 0][rl] = v.x; Bs[a_c + 1][rl] = v.y;
            Bs[a_c + 2][rl] = v.z; Bs[a_c + 3][rl] = v.w;
        }
        __syncthreads();
#pragma unroll
        for (int k = 0; k < BK; k++) {
            float am[TM], bn[TN];
#pragma unroll
            for (int i = 0; i < TM; i++) am[i] = As[k][ty * TM + i];
#pragma unroll
            for (int j = 0; j < TN; j++) bn[j] = Bs[k][tx * TN + j];
#pragma unroll
            for (int i = 0; i < TM; i++)
#pragma unroll
                for (int j = 0; j < TN; j++) acc[i][j] += am[i] * bn[j];
        }
        __syncthreads();
    }

    // epilogue: add bias, scatter to g_gx[dir][m][ng]
#pragma unroll
    for (int i = 0; i < TM; i++) {
        int m = m0 + ty * TM + i;
#pragma unroll
        for (int j = 0; j < TN; j++) {
            int n = n0 + tx * TN + j;
            int dir = n >> 11;
            int ng = n & 2047;
            float bias = (dir ? bwdb : fwdb)[ng];
            g_gx[(size_t)dir * SEQ * BSZ * NGATE + (size_t)m * NGATE + ng] = acc[i][j] + bias;
        }
    }
}

// ---------------- kernel 3: one recurrent step (both directions) ----------------
// grid: (HID/UJ, 2); 256 threads. CTA computes gates for UJ=8 hidden units
// (all 4 gates = 32 gate columns) for all 64 batch rows.
static const int UJ = 8;
__global__ void __launch_bounds__(256, 1)
k_step(const float* __restrict__ fwdW, const float* __restrict__ bwdW, int t) {
    int dir = blockIdx.y;
    int s = dir ? (SEQ - 1 - t) : t;
    const float* Wd = dir ? bwdW : fwdW;
    const float* hprev = g_hbuf + ((size_t)dir * 2 + (t & 1)) * (BSZ * HID);
    float* hnew        = g_hbuf + ((size_t)dir * 2 + ((t + 1) & 1)) * (BSZ * HID);
    int j0 = blockIdx.x * UJ;

    __shared__ __align__(16) float sh_h[BSZ][32];   // [b][k]  (broadcast reads)
    __shared__ __align__(16) float sh_w[32][36];    // [c][k]  padded: conflict-free LDS.128

    int tid = threadIdx.x;
    int wid = tid >> 5, lane = tid & 31;
    int g = lane >> 3, jj = lane & 7;               // lane -> (gate, unit)

    float acc[8];
#pragma unroll
    for (int i = 0; i < 8; i++) acc[i] = 0.0f;

    for (int k0 = 0; k0 < HID; k0 += 32) {
        // stage h_prev chunk: 64x32 floats
        {
            int r = tid >> 2;
            int c4 = (tid & 3) * 8;
            const float* src = hprev + (size_t)r * HID + k0 + c4;
            float4 v0 = *(const float4*)(src);
            float4 v1 = *(const float4*)(src + 4);
            *(float4*)&sh_h[r][c4]     = v0;
            *(float4*)&sh_h[r][c4 + 4] = v1;
        }
        // stage Wh slice chunk: 32 cols x 32 k (h-part of W: offset DIM)
        {
            int c  = tid >> 3;              // 0..31
            int kq = (tid & 7) * 4;         // 0..28
            int gg = c >> 3, jc = c & 7;
            const float* wsrc = Wd + ((size_t)(gg * HID + j0 + jc)) * DHID + DIM + k0 + kq;
            float4 v = *(const float4*)wsrc;
            *(float4*)&sh_w[c][kq] = v;
        }
        __syncthreads();

        int bbase = wid * 8;
#pragma unroll
        for (int k4 = 0; k4 < 32; k4 += 4) {
            float4 wv = *(const float4*)&sh_w[lane][k4];
#pragma unroll
            for (int b8 = 0; b8 < 8; b8++) {
                float4 hv = *(const float4*)&sh_h[bbase + b8][k4];
                acc[b8] += hv.x * wv.x;
                acc[b8] += hv.y * wv.y;
                acc[b8] += hv.z * wv.z;
                acc[b8] += hv.w * wv.w;
            }
        }
        __syncthreads();
    }

    // add precomputed x-projection (+bias) and apply nonlinearity
    size_t gxbase = ((size_t)dir * SEQ + s) * BSZ * NGATE;
    int col = g * HID + j0 + jj;
#pragma unroll
    for (int b8 = 0; b8 < 8; b8++) {
        int b = wid * 8 + b8;
        float val = acc[b8] + g_gx[gxbase + (size_t)b * NGATE + col];
        // gates live on lanes (g*8 + jj); gather all 4 for unit jj
        float gf = __shfl_sync(0xffffffffu, val, jj);
        float gi = __shfl_sync(0xffffffffu, val, 8 + jj);
        float gc = __shfl_sync(0xffffffffu, val, 16 + jj);
        float go = __shfl_sync(0xffffffffu, val, 24 + jj);
        if (g == 0) {
            float f  = 1.0f / (1.0f + __expf(-gf));
            float ii = 1.0f / (1.0f + __expf(-gi));
            float ct = tanhf(gc);
            float oo = 1.0f / (1.0f + __expf(-go));
            float cn = (f + ii) * ct;            // faithful: prev cell state unused
            float hh = oo * tanhf(cn);
            int j = j0 + jj;
            hnew[(size_t)b * HID + j] = hh;
            g_hist[(((size_t)dir * SEQ + s) * BSZ + b) * HID + j] = hh;
        }
    }
}

// ---------------- kernel 4: pooled = max_s tanh(h_fwd * h_bwd) ----------------
__global__ void k_pool() {
    int b = blockIdx.y;
    int h = blockIdx.x * 128 + threadIdx.x;
    float m = -2.0f;
    const float* pf = g_hist + ((size_t)b) * HID + h;                       // dir 0
    const float* pb = g_hist + (size_t)SEQ * BSZ * HID + (size_t)b * HID + h; // dir 1
    for (int s = 0; s < SEQ; s++) {
        float a = pf[(size_t)s * BSZ * HID];
        float c = pb[(size_t)s * BSZ * HID];
        float v = tanhf(a * c);
        m = fmaxf(m, v);
    }
    g_pooled[b * HID + h] = m;
}

// ---------------- kernel 5: out = pooled @ Wout^T + bout ----------------
__global__ void k_out(const float* __restrict__ Wout, const float* __restrict__ bout,
                      float* __restrict__ out) {
    int b = blockIdx.x;
    int c = threadIdx.x >> 5;      // 5 warps
    int lane = threadIdx.x & 31;
    float sum = 0.0f;
    for (int h = lane; h < HID; h += 32)
        sum += g_pooled[b * HID + h] * Wout[c * HID + h];
#pragma unroll
    for (int off = 16; off; off >>= 1)
        sum += __shfl_down_sync(0xffffffffu, sum, off);
    if (lane == 0) out[b * CLS + c] = sum + bout[c];
}

// ---------------- launcher ----------------
extern "C" void kernel_launch(void* const* d_in, const int* in_sizes, int n_in,
                              void* d_out, int out_size) {
    const int*   x     = (const int*)d_in[0];
    const float* embed = (const float*)d_in[1];
    const float* fwdW  = (const float*)d_in[2];
    const float* fwdb  = (const float*)d_in[3];
    const float* bwdW  = (const float*)d_in[4];
    const float* bwdb  = (const float*)d_in[5];
    const float* Wout  = (const float*)d_in[6];
    const float* bout  = (const float*)d_in[7];
    float* out = (float*)d_out;

    k_zero<<<(4 * BSZ * HID + 255) / 256, 256>>>();
    k_gather<<<MROWS, 128>>>(x, embed);
    k_gemm<<<dim3(NTOT / 128, MROWS / 128), 256>>>(fwdW, bwdW, fwdb, bwdb);
    for (int t = 0; t < SEQ; t++)
        k_step<<<dim3(HID / UJ, 2), 256>>>(fwdW, bwdW, t);
    k_pool<<<dim3(HID / 128, BSZ), 128>>>();
    k_out<<<BSZ, 5 * 32>>>(Wout, bout, out);
}

// round 2
// speedup vs baseline: 1.4173x; 1.4173x over previous
#include <cuda_runtime.h>

// ---------------- problem constants ----------------
static const int BSZ   = 64;
static const int SEQ   = 256;
static const int DIM   = 512;
static const int HID   = 512;
static const int DHID  = 1024;
static const int NGATE = 2048;          // 4*HID per direction
static const int MROWS = SEQ * BSZ;     // 16384
static const int NTOT  = 2 * NGATE;     // 4096
static const int CLS   = 5;
static const int NCTA  = 128;           // persistent CTAs (<=148 SMs: single wave)

// ---------------- device scratch ----------------
__device__ float g_xs  [MROWS * DIM];
__device__ float g_gx  [2L * SEQ * BSZ * NGATE];     // x-projection + bias
__device__ float g_hbuf[2 * 2 * BSZ * HID];          // [dir][parity][b][h]
__device__ float g_hist[2L * SEQ * BSZ * HID];
__device__ float g_pooled[BSZ * HID];
__device__ unsigned g_cnt[SEQ];                      // grid barrier counters

// packed fp32x2 FMA: d.lo += a.lo*b.lo; d.hi += a.hi*b.hi  (fp32 exact)
__device__ __forceinline__ void ffma2(unsigned long long& d,
                                      unsigned long long a, unsigned long long b) {
    asm volatile("fma.rn.f32x2 %0, %1, %2, %0;" : "+l"(d) : "l"(a), "l"(b));
}

// ---------------- kernel 0: zero state + barrier counters ----------------
__global__ void k_zero() {
    int i = blockIdx.x * blockDim.x + threadIdx.x;
    if (i < 4 * BSZ * HID) g_hbuf[i] = 0.0f;
    if (i < SEQ) g_cnt[i] = 0u;
}

// ---------------- kernel 1: embedding gather ----------------
__global__ void k_gather(const int* __restrict__ x, const float* __restrict__ embed) {
    int sb = blockIdx.x;                 // sb = s*BSZ + b
    int b = sb & (BSZ - 1);
    int s = sb >> 6;
    int tok = x[b * SEQ + s];
    const float4* src = (const float4*)(embed + (size_t)tok * DIM);
    float4* dst = (float4*)(g_xs + (size_t)sb * DIM);
    dst[threadIdx.x] = src[threadIdx.x]; // 128 threads * 4 floats
}

// ---------------- kernel 2: x-projection GEMM (FFMA2) ----------------
// C[m][n] = sum_k xs[m][k]*W(n)[k] + bias(n);  BM=128, BN=64, BK=32; pairs over k.
__global__ void __launch_bounds__(256, 2)
k_gemm(const float* __restrict__ fwdW, const float* __restrict__ bwdW,
       const float* __restrict__ fwdb, const float* __restrict__ bwdb) {
    __shared__ __align__(16) float2 As2[16][130];   // [k2][m] + pad
    __shared__ __align__(16) float2 Bs2[16][66];    // [k2][n] + pad

    int tid = threadIdx.x;
    int tx = tid & 15, ty = tid >> 4;
    int m0 = blockIdx.y * 128;
    int n0 = blockIdx.x * 64;

    unsigned long long acc[8][4];
#pragma unroll
    for (int i = 0; i < 8; i++)
#pragma unroll
        for (int j = 0; j < 4; j++) acc[i][j] = 0ull;   // bits == (0.f,0.f)

    for (int k0 = 0; k0 < DIM; k0 += 32) {
        // A tile: 128m x 32k
#pragma unroll
        for (int i = 0; i < 4; i++) {
            int idx = i * 256 + tid;
            int m = idx >> 3, k4 = idx & 7;
            float4 v = *(const float4*)(g_xs + (size_t)(m0 + m) * DIM + k0 + k4 * 4);
            As2[k4 * 2][m]     = make_float2(v.x, v.y);
            As2[k4 * 2 + 1][m] = make_float2(v.z, v.w);
        }
        // B tile: 64n x 32k  (n-tile never straddles dir boundary: 2048 % 64 == 0)
#pragma unroll
        for (int i = 0; i < 2; i++) {
            int idx = i * 256 + tid;
            int n = idx >> 3, k4 = idx & 7;
            int nn = n0 + n;
            int dir = nn >> 11, ng = nn & 2047;
            const float* Wrow = (dir ? bwdW : fwdW) + (size_t)ng * DHID;
            float4 v = *(const float4*)(Wrow + k0 + k4 * 4);
            Bs2[k4 * 2][n]     = make_float2(v.x, v.y);
            Bs2[k4 * 2 + 1][n] = make_float2(v.z, v.w);
        }
        __syncthreads();
#pragma unroll
        for (int k2 = 0; k2 < 16; k2++) {
            unsigned long long am[8], bn[4];
#pragma unroll
            for (int i = 0; i < 8; i++)
                am[i] = *(const unsigned long long*)&As2[k2][ty * 8 + i];
            ulonglong2 b01 = *(const ulonglong2*)&Bs2[k2][tx * 4];
            ulonglong2 b23 = *(const ulonglong2*)&Bs2[k2][tx * 4 + 2];
            bn[0] = b01.x; bn[1] = b01.y; bn[2] = b23.x; bn[3] = b23.y;
#pragma unroll
            for (int i = 0; i < 8; i++)
#pragma unroll
                for (int j = 0; j < 4; j++) ffma2(acc[i][j], am[i], bn[j]);
        }
        __syncthreads();
    }

#pragma unroll
    for (int i = 0; i < 8; i++) {
        int m = m0 + ty * 8 + i;
#pragma unroll
        for (int j = 0; j < 4; j++) {
            int n = n0 + tx * 4 + j;
            int dir = n >> 11, ng = n & 2047;
            float2 p = *(float2*)&acc[i][j];
            float val = p.x + p.y + (dir ? bwdb : fwdb)[ng];
            g_gx[(size_t)dir * SEQ * BSZ * NGATE + (size_t)m * NGATE + ng] = val;
        }
    }
}

// ---------------- kernel 3: persistent recurrence ----------------
// 128 CTAs: dir = bid>>6, unit block j0 = (bid&63)*8 -> 32 gate cols, 64 batches.
// Wh slice (32 cols x 512 k = 64 KB) resident in smem for all 256 steps.
// Grid barrier per step via g_cnt (all CTAs co-resident -> no deadlock).
extern __shared__ float4 dynsm[];

__global__ void __launch_bounds__(256, 1)
k_recur(const float* __restrict__ fwdW, const float* __restrict__ bwdW) {
    const int bid = blockIdx.x;
    const int dir = bid >> 6;
    const int j0 = (bid & 63) * 8;
    const float* Wd = dir ? bwdW : fwdW;
    const int tid = threadIdx.x, wid = tid >> 5, lane = tid & 31;
    const int g = lane >> 3, jj = lane & 7;

    float4* w4  = dynsm;                 // [k4][33] : [ (k4*33 + c) ], c = gate*8+unit
    float4* h4a = dynsm + 128 * 33;      // [b][17]  : chunk buffer A
    float4* h4b = h4a + 64 * 17;         // chunk buffer B

    // ---- preload Wh slice once (h-part of W: k offset DIM) ----
#pragma unroll
    for (int i = 0; i < 16; i++) {
        int idx = i * 256 + tid;         // 4096 float4
        int c = idx >> 7, k4 = idx & 127;
        int col = (c >> 3) * HID + j0 + (c & 7);
        w4[k4 * 33 + c] = *(const float4*)(Wd + (size_t)col * DHID + DIM + k4 * 4);
    }
    __syncthreads();

    const int sb = tid >> 4;             // staging row (0..15 per i-block -> b)
    const int sk = tid & 15;             // staging k4 within chunk

    for (int t = 0; t < SEQ; t++) {
        const int s = dir ? (SEQ - 1 - t) : t;
        const float* hprev = g_hbuf + ((size_t)dir * 2 + (t & 1)) * (BSZ * HID);
        float*       hnew  = g_hbuf + ((size_t)dir * 2 + ((t + 1) & 1)) * (BSZ * HID);

        // prefetch x-projection values (independent of h) into regs
        size_t gxbase = ((size_t)dir * SEQ + s) * BSZ * NGATE;
        const int col = g * HID + j0 + jj;
        float gxv[8];
#pragma unroll
        for (int b8 = 0; b8 < 8; b8++)
            gxv[b8] = g_gx[gxbase + (size_t)(wid * 8 + b8) * NGATE + col];

        unsigned long long acc[8];
#pragma unroll
        for (int i = 0; i < 8; i++) acc[i] = 0ull;

        // ---- software-pipelined chunks of 64 k: load h via L2 (L1 is stale) ----
        float4 pre[4];
#pragma unroll
        for (int i = 0; i < 4; i++) {
            int b = i * 16 + sb;
            pre[i] = __ldcg((const float4*)(hprev + (size_t)b * HID + sk * 4));
        }
        // stage chunk 0, prefetch chunk 1
#pragma unroll
        for (int i = 0; i < 4; i++) h4a[(i * 16 + sb) * 17 + sk] = pre[i];
#pragma unroll
        for (int i = 0; i < 4; i++) {
            int b = i * 16 + sb;
            pre[i] = __ldcg((const float4*)(hprev + (size_t)b * HID + 64 + sk * 4));
        }
        __syncthreads();

        float4* cur = h4a;
        float4* nxt = h4b;
        for (int kc = 0; kc < 8; kc++) {
            const int kbase = kc * 16;
#pragma unroll
            for (int k4 = 0; k4 < 16; k4++) {
                ulonglong2 wv = *(const ulonglong2*)&w4[(kbase + k4) * 33 + lane];
#pragma unroll
                for (int b8 = 0; b8 < 8; b8++) {
                    ulonglong2 hv = *(const ulonglong2*)&cur[(wid * 8 + b8) * 17 + k4];
                    ffma2(acc[b8], hv.x, wv.x);
                    ffma2(acc[b8], hv.y, wv.y);
                }
            }
            if (kc < 7) {
#pragma unroll
                for (int i = 0; i < 4; i++) nxt[(i * 16 + sb) * 17 + sk] = pre[i];
                if (kc < 6) {
                    const float* src = hprev + (kc + 2) * 64;
#pragma unroll
                    for (int i = 0; i < 4; i++) {
                        int b = i * 16 + sb;
                        pre[i] = __ldcg((const float4*)(src + (size_t)b * HID + sk * 4));
                    }
                }
            }
            __syncthreads();
            float4* tmp = cur; cur = nxt; nxt = tmp;
        }

        // ---- epilogue: combine pair halves, add gx, nonlinearity ----
#pragma unroll
        for (int b8 = 0; b8 < 8; b8++) {
            int b = wid * 8 + b8;
            float2 p = *(float2*)&acc[b8];
            float val = p.x + p.y + gxv[b8];
            float gf = __shfl_sync(0xffffffffu, val, jj);
            float gi = __shfl_sync(0xffffffffu, val, 8 + jj);
            float gc = __shfl_sync(0xffffffffu, val, 16 + jj);
            float go = __shfl_sync(0xffffffffu, val, 24 + jj);
            if (g == 0) {
                float f  = 1.0f / (1.0f + __expf(-gf));
                float ii = 1.0f / (1.0f + __expf(-gi));
                float ct = tanhf(gc);
                float oo = 1.0f / (1.0f + __expf(-go));
                float hh = oo * tanhf((f + ii) * ct);   // faithful: c_prev unused
                hnew[(size_t)b * HID + j0 + jj] = hh;
                g_hist[(((size_t)dir * SEQ + s) * BSZ + b) * HID + j0 + jj] = hh;
            }
        }

        // ---- grid barrier: all 128 CTAs finish step t ----
        __syncthreads();
        if (tid == 0) {
            __threadfence();
            atomicAdd(&g_cnt[t], 1u);
            while (*(volatile unsigned*)&g_cnt[t] < (unsigned)NCTA) { }
        }
        __syncthreads();
    }
}

// ---------------- kernel 4: pooled = max_s tanh(h_fwd * h_bwd) ----------------
__global__ void k_pool() {
    int b = blockIdx.y;
    int h = blockIdx.x * 128 + threadIdx.x;
    float m = -2.0f;
    const float* pf = g_hist + (size_t)b * HID + h;
    const float* pb = g_hist + (size_t)SEQ * BSZ * HID + (size_t)b * HID + h;
    for (int s = 0; s < SEQ; s++) {
        float a = pf[(size_t)s * BSZ * HID];
        float c = pb[(size_t)s * BSZ * HID];
        m = fmaxf(m, tanhf(a * c));
    }
    g_pooled[b * HID + h] = m;
}

// ---------------- kernel 5: out = pooled @ Wout^T + bout ----------------
__global__ void k_out(const float* __restrict__ Wout, const float* __restrict__ bout,
                      float* __restrict__ out) {
    int b = blockIdx.x;
    int c = threadIdx.x >> 5;
    int lane = threadIdx.x & 31;
    float sum = 0.0f;
    for (int h = lane; h < HID; h += 32)
        sum += g_pooled[b * HID + h] * Wout[c * HID + h];
#pragma unroll
    for (int off = 16; off; off >>= 1)
        sum += __shfl_down_sync(0xffffffffu, sum, off);
    if (lane == 0) out[b * CLS + c] = sum + bout[c];
}

// ---------------- launcher ----------------
static const int RECUR_SMEM = (128 * 33 + 2 * 64 * 17) * 16;   // 102400 B

extern "C" void kernel_launch(void* const* d_in, const int* in_sizes, int n_in,
                              void* d_out, int out_size) {
    const int*   x     = (const int*)d_in[0];
    const float* embed = (const float*)d_in[1];
    const float* fwdW  = (const float*)d_in[2];
    const float* fwdb  = (const float*)d_in[3];
    const float* bwdW  = (const float*)d_in[4];
    const float* bwdb  = (const float*)d_in[5];
    const float* Wout  = (const float*)d_in[6];
    const float* bout  = (const float*)d_in[7];
    float* out = (float*)d_out;

    cudaFuncSetAttribute(k_recur, cudaFuncAttributeMaxDynamicSharedMemorySize, RECUR_SMEM);

    k_zero<<<(4 * BSZ * HID + 255) / 256, 256>>>();
    k_gather<<<MROWS, 128>>>(x, embed);
    k_gemm<<<dim3(NTOT / 64, MROWS / 128), 256>>>(fwdW, bwdW, fwdb, bwdb);
    k_recur<<<NCTA, 256, RECUR_SMEM>>>(fwdW, bwdW);
    k_pool<<<dim3(HID / 128, BSZ), 128>>>();
    k_out<<<BSZ, 5 * 32>>>(Wout, bout, out);
}